// round 3
// baseline (speedup 1.0000x reference)
#include <cuda_runtime.h>
#include <cstdint>
#include <cstddef>

#define N_USERS   100000
#define N_NODES   500000
#define DIM       64
#define N_EDGES   2000000
#define BATCH     4096

// -------- device scratch (static, allocation-free) --------
__device__ float    g_XA[(size_t)N_NODES * DIM];   // layer-1 output (f1 rows valid)
__device__ float    g_XB[(size_t)N_NODES * DIM];   // layer-2 output (f2 rows valid)
__device__ float    g_XC[(size_t)N_NODES * DIM];   // layer-3 output (f3 rows valid)
__device__ float    g_dinv[N_NODES];
__device__ unsigned g_deg[N_NODES];
__device__ float    g_norm[N_EDGES];
__device__ char     g_f1[N_NODES];                 // rows needed at layer 1/2/3 (f3⊆f2⊆f1)
__device__ char     g_f2[N_NODES];
__device__ char     g_f3[N_NODES];
__device__ float    g_acc[(size_t)3 * BATCH * DIM]; // batch accumulators [user|pos|neg]

// -------- init counters + flags --------
__global__ void k_init() {
    int i = blockIdx.x * blockDim.x + threadIdx.x;
    if (i < N_NODES) {
        g_deg[i] = 0u;
        g_f1[i] = 0; g_f2[i] = 0; g_f3[i] = 0;
    }
}

__global__ void k_deg(const int* __restrict__ dst) {
    int e = blockIdx.x * blockDim.x + threadIdx.x;
    if (e < N_EDGES) atomicAdd(&g_deg[dst[e]], 1u);
}

__global__ void k_dinv() {
    int i = blockIdx.x * blockDim.x + threadIdx.x;
    if (i < N_NODES) {
        unsigned d = g_deg[i];
        g_dinv[i] = d ? rsqrtf((float)d) : 0.0f;
    }
}

__global__ void k_norm(const int* __restrict__ src, const int* __restrict__ dst) {
    int e = blockIdx.x * blockDim.x + threadIdx.x;
    if (e < N_EDGES) g_norm[e] = g_dinv[src[e]] * g_dinv[dst[e]];
}

// -------- needed-node flags --------
__global__ void k_mark_batch(const int* __restrict__ u,
                             const int* __restrict__ p,
                             const int* __restrict__ n) {
    int t = blockIdx.x * blockDim.x + threadIdx.x;
    if (t >= 3 * BATCH) return;
    int idx = (t < BATCH) ? u[t]
            : (t < 2 * BATCH) ? p[t - BATCH]
                              : n[t - 2 * BATCH];
    g_f1[idx] = 1; g_f2[idx] = 1; g_f3[idx] = 1;
}

// if dst needed at layer L, its sources are needed at layer L-1
__global__ void k_expand(const int* __restrict__ src, const int* __restrict__ dst,
                         const char* __restrict__ f_next, char* __restrict__ f_prev) {
    int e = blockIdx.x * blockDim.x + threadIdx.x;
    if (e < N_EDGES && f_next[dst[e]]) f_prev[src[e]] = 1;
}

// -------- zero only flagged rows of a buffer --------
__global__ void k_zero_flagged(float* __restrict__ y, const char* __restrict__ flag) {
    unsigned gid = blockIdx.x * blockDim.x + threadIdx.x;
    unsigned node = gid >> 4;                       // 16 float4-chunks per row
    if (node >= N_NODES) return;
    if (!flag[node]) return;
    ((float4*)y)[(size_t)node * 16 + (gid & 15)] = make_float4(0.f, 0.f, 0.f, 0.f);
}

// -------- flag-gated edge-parallel propagation --------
// 16 threads per edge, float4 gather + red.global.add.v4.f32 scatter
__global__ void k_prop(const float* __restrict__ x, float* __restrict__ y,
                       const int* __restrict__ src, const int* __restrict__ dst,
                       const char* __restrict__ flag) {
    unsigned gid = blockIdx.x * blockDim.x + threadIdx.x;
    unsigned e = gid >> 4;
    if (e >= N_EDGES) return;
    int d = __ldg(dst + e);
    if (!flag[d]) return;                           // early-exit before heavy loads
    int lane = gid & 15;

    int   s = __ldg(src + e);
    float w = __ldg(g_norm + e);
    float4 v = __ldg((const float4*)x + (size_t)s * 16 + lane);
    float4* a = (float4*)y + (size_t)d * 16 + lane;
    asm volatile("red.global.add.v4.f32 [%0], {%1, %2, %3, %4};"
                 :: "l"(a), "f"(v.x * w), "f"(v.y * w), "f"(v.z * w), "f"(v.w * w)
                 : "memory");
}

// -------- batch accumulators --------
__global__ void k_init_acc(const float* __restrict__ emb,
                           const int* __restrict__ u,
                           const int* __restrict__ p,
                           const int* __restrict__ n) {
    int t = blockIdx.x * blockDim.x + threadIdx.x;
    if (t >= 3 * BATCH * (DIM / 4)) return;
    int row = t >> 4, c = t & 15;
    int idx = (row < BATCH) ? u[row]
            : (row < 2 * BATCH) ? p[row - BATCH]
                                : n[row - 2 * BATCH];
    ((float4*)g_acc)[t] = __ldg((const float4*)emb + (size_t)idx * 16 + c);
}

__global__ void k_gather_add(const float* __restrict__ x,
                             const int* __restrict__ u,
                             const int* __restrict__ p,
                             const int* __restrict__ n) {
    int t = blockIdx.x * blockDim.x + threadIdx.x;
    if (t >= 3 * BATCH * (DIM / 4)) return;
    int row = t >> 4, c = t & 15;
    int idx = (row < BATCH) ? u[row]
            : (row < 2 * BATCH) ? p[row - BATCH]
                                : n[row - 2 * BATCH];
    float4 v = __ldg((const float4*)x + (size_t)idx * 16 + c);
    float4* a = (float4*)g_acc + t;
    float4 av = *a;
    av.x += v.x; av.y += v.y; av.z += v.z; av.w += v.w;
    *a = av;
}

__global__ void k_zero_out(float* out) {
    if (threadIdx.x == 0 && blockIdx.x == 0) out[0] = 0.0f;
}

// -------- final BPR + L2 loss: one warp per batch element --------
__global__ void k_loss(const float* __restrict__ emb,
                       const int* __restrict__ user,
                       const int* __restrict__ pos,
                       const int* __restrict__ neg,
                       float* __restrict__ out) {
    int w = (blockIdx.x * blockDim.x + threadIdx.x) >> 5;
    int lane = threadIdx.x & 31;
    if (w >= BATCH) return;

    const float* U  = g_acc + (size_t)w * DIM;
    const float* P  = g_acc + (size_t)(BATCH + w) * DIM;
    const float* Nn = g_acc + (size_t)(2 * BATCH + w) * DIM;

    int ui = user[w], pi = pos[w], ni = neg[w];

    float pd = 0.f, nd = 0.f, sq = 0.f;
#pragma unroll
    for (int k = 0; k < 2; k++) {
        int j = lane + 32 * k;
        float uu = U[j], pp = P[j], nn = Nn[j];
        pd += uu * pp;
        nd += uu * nn;
        float a = __ldg(emb + (size_t)ui * DIM + j);
        float b = __ldg(emb + (size_t)pi * DIM + j);
        float c = __ldg(emb + (size_t)ni * DIM + j);
        sq += a * a + b * b + c * c;
    }
#pragma unroll
    for (int o = 16; o; o >>= 1) {
        pd += __shfl_xor_sync(0xffffffffu, pd, o);
        nd += __shfl_xor_sync(0xffffffffu, nd, o);
        sq += __shfl_xor_sync(0xffffffffu, sq, o);
    }
    if (lane == 0) {
        // acc rows = sums over 4 stacked layers; mean /4 each side -> dot scales 1/16
        float z = (nd - pd) * 0.0625f;
        float sp = fmaxf(z, 0.f) + log1pf(expf(-fabsf(z)));   // softplus(neg - pos)
        atomicAdd(out, (sp + 5e-5f * sq) * (1.0f / BATCH));
    }
}

extern "C" void kernel_launch(void* const* d_in, const int* in_sizes, int n_in,
                              void* d_out, int out_size) {
    const float* emb  = (const float*)d_in[0];
    const int*   edge = (const int*)d_in[1];
    const int*   src  = edge;
    const int*   dst  = edge + N_EDGES;
    const int*   user = (const int*)d_in[2];
    const int*   pos  = (const int*)d_in[3];
    const int*   neg  = (const int*)d_in[4];
    float*       out  = (float*)d_out;

    const int T = 256;
    const int G_NODES = (N_NODES + T - 1) / T;
    const int G_EDGES = (N_EDGES + T - 1) / T;
    const int G_PROP  = (int)(((size_t)N_EDGES * 16 + T - 1) / T);     // 125000
    const int G_ZEROF = (int)(((size_t)N_NODES * 16 + T - 1) / T);     // 31250
    const int G_ACC   = (3 * BATCH * (DIM / 4) + T - 1) / T;
    const int G_MARK  = (3 * BATCH + T - 1) / T;

    // degree -> dinv -> per-edge norm
    k_init<<<G_NODES, T>>>();
    k_deg<<<G_EDGES, T>>>(dst);
    k_dinv<<<G_NODES, T>>>();
    k_norm<<<G_EDGES, T>>>(src, dst);

    // needed-node flags: f3 = batch; f2 = f3 ∪ src(in-edges of f3); f1 likewise from f2
    k_mark_batch<<<G_MARK, T>>>(user, pos, neg);
    k_expand<<<G_EDGES, T>>>(src, dst, g_f3, g_f2);
    k_expand<<<G_EDGES, T>>>(src, dst, g_f2, g_f1);

    // zero only the rows each layer will write
    k_zero_flagged<<<G_ZEROF, T>>>(g_XA, g_f1);
    k_zero_flagged<<<G_ZEROF, T>>>(g_XB, g_f2);
    k_zero_flagged<<<G_ZEROF, T>>>(g_XC, g_f3);

    // layer-0 term of the stacked mean
    k_init_acc<<<G_ACC, T>>>(emb, user, pos, neg);

    // layer 1: emb -> XA (f1 rows)
    k_prop<<<G_PROP, T>>>(emb, g_XA, src, dst, g_f1);
    k_gather_add<<<G_ACC, T>>>(g_XA, user, pos, neg);

    // layer 2: XA -> XB (f2 rows; all needed sources are f1 rows)
    k_prop<<<G_PROP, T>>>(g_XA, g_XB, src, dst, g_f2);
    k_gather_add<<<G_ACC, T>>>(g_XB, user, pos, neg);

    // layer 3: XB -> XC (f3 = batch rows)
    k_prop<<<G_PROP, T>>>(g_XB, g_XC, src, dst, g_f3);
    k_gather_add<<<G_ACC, T>>>(g_XC, user, pos, neg);

    // loss
    k_zero_out<<<1, 1>>>(out);
    k_loss<<<BATCH / 8, T>>>(emb, user, pos, neg, out);
}

// round 4
// speedup vs baseline: 3.1929x; 3.1929x over previous
#include <cuda_runtime.h>
#include <cstdint>
#include <cstddef>

#define N_USERS   100000
#define N_NODES   500000
#define DIM       64
#define N_EDGES   2000000
#define BATCH     4096

// -------- device scratch (static, allocation-free) --------
// NOTE: these symbols must NEVER appear in host code (host shadow address is
// ATS-reachable host memory on GB300 -> silently correct but 40x slower).
__device__ float    g_XA[(size_t)N_NODES * DIM];   // layer-1 output (f1 rows valid)
__device__ float    g_XB[(size_t)N_NODES * DIM];   // layer-2 output (f2 rows valid)
__device__ float    g_XC[(size_t)N_NODES * DIM];   // layer-3 output (f3 rows valid)
__device__ float    g_dinv[N_NODES];
__device__ unsigned g_deg[N_NODES];
__device__ float    g_norm[N_EDGES];
__device__ char     g_f1[N_NODES];                 // rows needed at layer 1/2/3 (f3⊆f2⊆f1)
__device__ char     g_f2[N_NODES];
__device__ char     g_f3[N_NODES];
__device__ float    g_acc[(size_t)3 * BATCH * DIM]; // batch accumulators [user|pos|neg]

__device__ __forceinline__ float* xbuf(int sel) {
    return sel == 1 ? g_XA : (sel == 2 ? g_XB : g_XC);
}
__device__ __forceinline__ char* fbuf(int sel) {
    return sel == 1 ? g_f1 : (sel == 2 ? g_f2 : g_f3);
}

// -------- init counters + flags --------
__global__ void k_init() {
    int i = blockIdx.x * blockDim.x + threadIdx.x;
    if (i < N_NODES) {
        g_deg[i] = 0u;
        g_f1[i] = 0; g_f2[i] = 0; g_f3[i] = 0;
    }
}

__global__ void k_deg(const int* __restrict__ dst) {
    int e = blockIdx.x * blockDim.x + threadIdx.x;
    if (e < N_EDGES) atomicAdd(&g_deg[dst[e]], 1u);
}

__global__ void k_dinv() {
    int i = blockIdx.x * blockDim.x + threadIdx.x;
    if (i < N_NODES) {
        unsigned d = g_deg[i];
        g_dinv[i] = d ? rsqrtf((float)d) : 0.0f;
    }
}

__global__ void k_norm(const int* __restrict__ src, const int* __restrict__ dst) {
    int e = blockIdx.x * blockDim.x + threadIdx.x;
    if (e < N_EDGES) g_norm[e] = g_dinv[src[e]] * g_dinv[dst[e]];
}

// -------- needed-node flags --------
__global__ void k_mark_batch(const int* __restrict__ u,
                             const int* __restrict__ p,
                             const int* __restrict__ n) {
    int t = blockIdx.x * blockDim.x + threadIdx.x;
    if (t >= 3 * BATCH) return;
    int idx = (t < BATCH) ? u[t]
            : (t < 2 * BATCH) ? p[t - BATCH]
                              : n[t - 2 * BATCH];
    g_f1[idx] = 1; g_f2[idx] = 1; g_f3[idx] = 1;
}

// if dst needed at layer L, its sources are needed at layer L-1
__global__ void k_expand(const int* __restrict__ src, const int* __restrict__ dst,
                         int f_next_sel, int f_prev_sel) {
    int e = blockIdx.x * blockDim.x + threadIdx.x;
    if (e >= N_EDGES) return;
    const char* fn = fbuf(f_next_sel);
    char*       fp = fbuf(f_prev_sel);
    if (fn[dst[e]]) fp[src[e]] = 1;
}

// -------- zero only flagged rows of a buffer --------
__global__ void k_zero_flagged(int ysel, int fsel) {
    unsigned gid = blockIdx.x * blockDim.x + threadIdx.x;
    unsigned node = gid >> 4;                       // 16 float4-chunks per row
    if (node >= N_NODES) return;
    if (!fbuf(fsel)[node]) return;
    ((float4*)xbuf(ysel))[(size_t)node * 16 + (gid & 15)] =
        make_float4(0.f, 0.f, 0.f, 0.f);
}

// -------- flag-gated edge-parallel propagation --------
// 16 threads per edge, float4 gather + red.global.add.v4.f32 scatter
__global__ void k_prop(const float* __restrict__ emb, int xsel, int ysel, int fsel,
                       const int* __restrict__ src, const int* __restrict__ dst) {
    unsigned gid = blockIdx.x * blockDim.x + threadIdx.x;
    unsigned e = gid >> 4;
    if (e >= N_EDGES) return;
    int d = __ldg(dst + e);
    if (!fbuf(fsel)[d]) return;                     // early-exit before heavy loads
    int lane = gid & 15;

    const float* x = (xsel == 0) ? emb : xbuf(xsel);
    float*       y = xbuf(ysel);

    int   s = __ldg(src + e);
    float w = __ldg(g_norm + e);
    float4 v = __ldg((const float4*)x + (size_t)s * 16 + lane);
    float4* a = (float4*)y + (size_t)d * 16 + lane;
    asm volatile("red.global.add.v4.f32 [%0], {%1, %2, %3, %4};"
                 :: "l"(a), "f"(v.x * w), "f"(v.y * w), "f"(v.z * w), "f"(v.w * w)
                 : "memory");
}

// -------- batch accumulators --------
__global__ void k_init_acc(const float* __restrict__ emb,
                           const int* __restrict__ u,
                           const int* __restrict__ p,
                           const int* __restrict__ n) {
    int t = blockIdx.x * blockDim.x + threadIdx.x;
    if (t >= 3 * BATCH * (DIM / 4)) return;
    int row = t >> 4, c = t & 15;
    int idx = (row < BATCH) ? u[row]
            : (row < 2 * BATCH) ? p[row - BATCH]
                                : n[row - 2 * BATCH];
    ((float4*)g_acc)[t] = __ldg((const float4*)emb + (size_t)idx * 16 + c);
}

__global__ void k_gather_add(int xsel,
                             const int* __restrict__ u,
                             const int* __restrict__ p,
                             const int* __restrict__ n) {
    int t = blockIdx.x * blockDim.x + threadIdx.x;
    if (t >= 3 * BATCH * (DIM / 4)) return;
    int row = t >> 4, c = t & 15;
    int idx = (row < BATCH) ? u[row]
            : (row < 2 * BATCH) ? p[row - BATCH]
                                : n[row - 2 * BATCH];
    const float* x = xbuf(xsel);
    float4 v = __ldg((const float4*)x + (size_t)idx * 16 + c);
    float4* a = (float4*)g_acc + t;
    float4 av = *a;
    av.x += v.x; av.y += v.y; av.z += v.z; av.w += v.w;
    *a = av;
}

__global__ void k_zero_out(float* out) {
    if (threadIdx.x == 0 && blockIdx.x == 0) out[0] = 0.0f;
}

// -------- final BPR + L2 loss: one warp per batch element --------
__global__ void k_loss(const float* __restrict__ emb,
                       const int* __restrict__ user,
                       const int* __restrict__ pos,
                       const int* __restrict__ neg,
                       float* __restrict__ out) {
    int w = (blockIdx.x * blockDim.x + threadIdx.x) >> 5;
    int lane = threadIdx.x & 31;
    if (w >= BATCH) return;

    const float* U  = g_acc + (size_t)w * DIM;
    const float* P  = g_acc + (size_t)(BATCH + w) * DIM;
    const float* Nn = g_acc + (size_t)(2 * BATCH + w) * DIM;

    int ui = user[w], pi = pos[w], ni = neg[w];

    float pd = 0.f, nd = 0.f, sq = 0.f;
#pragma unroll
    for (int k = 0; k < 2; k++) {
        int j = lane + 32 * k;
        float uu = U[j], pp = P[j], nn = Nn[j];
        pd += uu * pp;
        nd += uu * nn;
        float a = __ldg(emb + (size_t)ui * DIM + j);
        float b = __ldg(emb + (size_t)pi * DIM + j);
        float c = __ldg(emb + (size_t)ni * DIM + j);
        sq += a * a + b * b + c * c;
    }
#pragma unroll
    for (int o = 16; o; o >>= 1) {
        pd += __shfl_xor_sync(0xffffffffu, pd, o);
        nd += __shfl_xor_sync(0xffffffffu, nd, o);
        sq += __shfl_xor_sync(0xffffffffu, sq, o);
    }
    if (lane == 0) {
        // acc rows = sums over 4 stacked layers; mean /4 each side -> dot scales 1/16
        float z = (nd - pd) * 0.0625f;
        float sp = fmaxf(z, 0.f) + log1pf(expf(-fabsf(z)));   // softplus(neg - pos)
        atomicAdd(out, (sp + 5e-5f * sq) * (1.0f / BATCH));
    }
}

extern "C" void kernel_launch(void* const* d_in, const int* in_sizes, int n_in,
                              void* d_out, int out_size) {
    const float* emb  = (const float*)d_in[0];
    const int*   edge = (const int*)d_in[1];
    const int*   src  = edge;
    const int*   dst  = edge + N_EDGES;
    const int*   user = (const int*)d_in[2];
    const int*   pos  = (const int*)d_in[3];
    const int*   neg  = (const int*)d_in[4];
    float*       out  = (float*)d_out;

    const int T = 256;
    const int G_NODES = (N_NODES + T - 1) / T;
    const int G_EDGES = (N_EDGES + T - 1) / T;
    const int G_PROP  = (int)(((size_t)N_EDGES * 16 + T - 1) / T);     // 125000
    const int G_ZEROF = (int)(((size_t)N_NODES * 16 + T - 1) / T);     // 31250
    const int G_ACC   = (3 * BATCH * (DIM / 4) + T - 1) / T;
    const int G_MARK  = (3 * BATCH + T - 1) / T;

    // degree -> dinv -> per-edge norm
    k_init<<<G_NODES, T>>>();
    k_deg<<<G_EDGES, T>>>(dst);
    k_dinv<<<G_NODES, T>>>();
    k_norm<<<G_EDGES, T>>>(src, dst);

    // needed-node flags: f3 = batch; f2 = f3 ∪ src(in-edges of f3); f1 likewise from f2
    k_mark_batch<<<G_MARK, T>>>(user, pos, neg);
    k_expand<<<G_EDGES, T>>>(src, dst, 3, 2);
    k_expand<<<G_EDGES, T>>>(src, dst, 2, 1);

    // zero only the rows each layer will write
    k_zero_flagged<<<G_ZEROF, T>>>(1, 1);
    k_zero_flagged<<<G_ZEROF, T>>>(2, 2);
    k_zero_flagged<<<G_ZEROF, T>>>(3, 3);

    // layer-0 term of the stacked mean
    k_init_acc<<<G_ACC, T>>>(emb, user, pos, neg);

    // layer 1: emb -> XA (f1 rows)
    k_prop<<<G_PROP, T>>>(emb, 0, 1, 1, src, dst);
    k_gather_add<<<G_ACC, T>>>(1, user, pos, neg);

    // layer 2: XA -> XB (f2 rows; all needed sources are f1 rows)
    k_prop<<<G_PROP, T>>>(emb, 1, 2, 2, src, dst);
    k_gather_add<<<G_ACC, T>>>(2, user, pos, neg);

    // layer 3: XB -> XC (f3 = batch rows)
    k_prop<<<G_PROP, T>>>(emb, 2, 3, 3, src, dst);
    k_gather_add<<<G_ACC, T>>>(3, user, pos, neg);

    // loss
    k_zero_out<<<1, 1>>>(out);
    k_loss<<<BATCH / 8, T>>>(emb, user, pos, neg, out);
}

// round 5
// speedup vs baseline: 6.3652x; 1.9936x over previous
#include <cuda_runtime.h>
#include <cstdint>
#include <cstddef>

#define N_USERS   100000
#define N_NODES   500000
#define DIM       64
#define N_EDGES   2000000
#define BATCH     4096

// -------- device scratch (static, allocation-free) --------
// NOTE: never reference these symbols from host code (GB300 ATS would silently
// route through the host shadow at 200GB/s). All access via device selectors.
__device__ float    g_XA[(size_t)N_NODES * DIM];
__device__ float    g_XB[(size_t)N_NODES * DIM];
__device__ float    g_XC[(size_t)N_NODES * DIM];
__device__ float    g_dinv[N_NODES];
__device__ unsigned g_deg[N_NODES];
__device__ int      g_f[3][N_NODES];       // needed-node flags per layer (0=L1,1=L2,2=L3)
__device__ int      g_nl[3][N_NODES];      // compact node lists
__device__ int      g_ncnt[3];
__device__ int      g_le_src[3][N_EDGES];  // compact edge lists
__device__ int      g_le_dst[3][N_EDGES];
__device__ float    g_le_w[3][N_EDGES];
__device__ int      g_ecnt[3];
__device__ float    g_acc[(size_t)3 * BATCH * DIM]; // batch accumulators [user|pos|neg]

__device__ __forceinline__ float* xbuf(int sel) {
    return sel == 1 ? g_XA : (sel == 2 ? g_XB : g_XC);
}

// -------- init counters + flags --------
__global__ void k_init() {
    int i = blockIdx.x * blockDim.x + threadIdx.x;
    if (i < N_NODES) {
        g_deg[i] = 0u;
        g_f[0][i] = 0; g_f[1][i] = 0; g_f[2][i] = 0;
    }
    if (i < 3) { g_ncnt[i] = 0; g_ecnt[i] = 0; }
}

__global__ void k_deg(const int* __restrict__ dst) {
    int e = blockIdx.x * blockDim.x + threadIdx.x;
    if (e < N_EDGES) atomicAdd(&g_deg[dst[e]], 1u);
}

__global__ void k_dinv() {
    int i = blockIdx.x * blockDim.x + threadIdx.x;
    if (i < N_NODES) {
        unsigned d = g_deg[i];
        g_dinv[i] = d ? rsqrtf((float)d) : 0.0f;
    }
}

// mark batch nodes in all 3 flag sets + node lists (atomicExch dedup)
__global__ void k_mark_batch(const int* __restrict__ u,
                             const int* __restrict__ p,
                             const int* __restrict__ n) {
    int t = blockIdx.x * blockDim.x + threadIdx.x;
    if (t >= 3 * BATCH) return;
    int idx = (t < BATCH) ? u[t]
            : (t < 2 * BATCH) ? p[t - BATCH]
                              : n[t - 2 * BATCH];
#pragma unroll
    for (int L = 0; L < 3; L++) {
        if (atomicExch(&g_f[L][idx], 1) == 0) {
            int s = atomicAdd(&g_ncnt[L], 1);
            g_nl[L][s] = idx;
        }
    }
}

// compaction: gate on f[gate], append passing edges (src,dst,w) to list[gate];
// optionally mark sources as needed for the previous layer (+node list)
__global__ void k_compact(const int* __restrict__ src, const int* __restrict__ dst,
                          int gate, int prev, int has_prev) {
    int e = blockIdx.x * blockDim.x + threadIdx.x;
    if (e >= N_EDGES) return;
    int d = __ldg(dst + e);
    if (!g_f[gate][d]) return;
    int s = __ldg(src + e);
    float w = g_dinv[s] * g_dinv[d];
    int slot = atomicAdd(&g_ecnt[gate], 1);
    g_le_src[gate][slot] = s;
    g_le_dst[gate][slot] = d;
    g_le_w[gate][slot]   = w;
    if (has_prev) {
        if (atomicExch(&g_f[prev][s], 1) == 0) {
            int ns = atomicAdd(&g_ncnt[prev], 1);
            g_nl[prev][ns] = s;
        }
    }
}

// zero exactly the rows in node list lsel of buffer xsel (grid-stride)
__global__ void k_zero_list(int xsel, int lsel) {
    int n16 = g_ncnt[lsel] * 16;
    float4* y = (float4*)xbuf(xsel);
    int stride = gridDim.x * blockDim.x;
    for (int t = blockIdx.x * blockDim.x + threadIdx.x; t < n16; t += stride) {
        int node = g_nl[lsel][t >> 4];
        y[(size_t)node * 16 + (t & 15)] = make_float4(0.f, 0.f, 0.f, 0.f);
    }
}

// propagation over compact edge list: 16 threads/edge, grid-stride
__global__ void k_prop_list(const float* __restrict__ emb, int xsel, int ysel, int lsel) {
    int m = g_ecnt[lsel] * 16;
    const float* x = (xsel == 0) ? emb : xbuf(xsel);
    float*       y = xbuf(ysel);
    int stride = gridDim.x * blockDim.x;
    for (int t = blockIdx.x * blockDim.x + threadIdx.x; t < m; t += stride) {
        int e = t >> 4, lane = t & 15;
        int   s = __ldg(&g_le_src[lsel][e]);
        int   d = __ldg(&g_le_dst[lsel][e]);
        float w = __ldg(&g_le_w[lsel][e]);
        float4 v = __ldg((const float4*)x + (size_t)s * 16 + lane);
        float4* a = (float4*)y + (size_t)d * 16 + lane;
        asm volatile("red.global.add.v4.f32 [%0], {%1, %2, %3, %4};"
                     :: "l"(a), "f"(v.x * w), "f"(v.y * w), "f"(v.z * w), "f"(v.w * w)
                     : "memory");
    }
}

// -------- batch accumulators --------
__global__ void k_init_acc(const float* __restrict__ emb,
                           const int* __restrict__ u,
                           const int* __restrict__ p,
                           const int* __restrict__ n) {
    int t = blockIdx.x * blockDim.x + threadIdx.x;
    if (t >= 3 * BATCH * (DIM / 4)) return;
    int row = t >> 4, c = t & 15;
    int idx = (row < BATCH) ? u[row]
            : (row < 2 * BATCH) ? p[row - BATCH]
                                : n[row - 2 * BATCH];
    ((float4*)g_acc)[t] = __ldg((const float4*)emb + (size_t)idx * 16 + c);
}

__global__ void k_gather_add(int xsel,
                             const int* __restrict__ u,
                             const int* __restrict__ p,
                             const int* __restrict__ n) {
    int t = blockIdx.x * blockDim.x + threadIdx.x;
    if (t >= 3 * BATCH * (DIM / 4)) return;
    int row = t >> 4, c = t & 15;
    int idx = (row < BATCH) ? u[row]
            : (row < 2 * BATCH) ? p[row - BATCH]
                                : n[row - 2 * BATCH];
    float4 v = __ldg((const float4*)xbuf(xsel) + (size_t)idx * 16 + c);
    float4* a = (float4*)g_acc + t;
    float4 av = *a;
    av.x += v.x; av.y += v.y; av.z += v.z; av.w += v.w;
    *a = av;
}

__global__ void k_zero_out(float* out) {
    if (threadIdx.x == 0 && blockIdx.x == 0) out[0] = 0.0f;
}

// -------- final BPR + L2 loss: one warp per batch element --------
__global__ void k_loss(const float* __restrict__ emb,
                       const int* __restrict__ user,
                       const int* __restrict__ pos,
                       const int* __restrict__ neg,
                       float* __restrict__ out) {
    int w = (blockIdx.x * blockDim.x + threadIdx.x) >> 5;
    int lane = threadIdx.x & 31;
    if (w >= BATCH) return;

    const float* U  = g_acc + (size_t)w * DIM;
    const float* P  = g_acc + (size_t)(BATCH + w) * DIM;
    const float* Nn = g_acc + (size_t)(2 * BATCH + w) * DIM;

    int ui = user[w], pi = pos[w], ni = neg[w];

    float pd = 0.f, nd = 0.f, sq = 0.f;
#pragma unroll
    for (int k = 0; k < 2; k++) {
        int j = lane + 32 * k;
        float uu = U[j], pp = P[j], nn = Nn[j];
        pd += uu * pp;
        nd += uu * nn;
        float a = __ldg(emb + (size_t)ui * DIM + j);
        float b = __ldg(emb + (size_t)pi * DIM + j);
        float c = __ldg(emb + (size_t)ni * DIM + j);
        sq += a * a + b * b + c * c;
    }
#pragma unroll
    for (int o = 16; o; o >>= 1) {
        pd += __shfl_xor_sync(0xffffffffu, pd, o);
        nd += __shfl_xor_sync(0xffffffffu, nd, o);
        sq += __shfl_xor_sync(0xffffffffu, sq, o);
    }
    if (lane == 0) {
        // acc rows = sums over 4 stacked layers; mean /4 each side -> dot scales 1/16
        float z = (nd - pd) * 0.0625f;
        float sp = fmaxf(z, 0.f) + log1pf(expf(-fabsf(z)));   // softplus(neg - pos)
        atomicAdd(out, (sp + 5e-5f * sq) * (1.0f / BATCH));
    }
}

extern "C" void kernel_launch(void* const* d_in, const int* in_sizes, int n_in,
                              void* d_out, int out_size) {
    const float* emb  = (const float*)d_in[0];
    const int*   edge = (const int*)d_in[1];
    const int*   src  = edge;
    const int*   dst  = edge + N_EDGES;
    const int*   user = (const int*)d_in[2];
    const int*   pos  = (const int*)d_in[3];
    const int*   neg  = (const int*)d_in[4];
    float*       out  = (float*)d_out;

    const int T = 256;
    const int G_NODES = (N_NODES + T - 1) / T;
    const int G_EDGES = (N_EDGES + T - 1) / T;
    const int G_ACC   = (3 * BATCH * (DIM / 4) + T - 1) / T;
    const int G_MARK  = (3 * BATCH + T - 1) / T;
    const int G_PROP  = 2048;    // grid-stride persistent-ish
    const int G_ZERO  = 1024;

    // degree -> dinv
    k_init<<<G_NODES, T>>>();
    k_deg<<<G_EDGES, T>>>(dst);
    k_dinv<<<G_NODES, T>>>();

    // flags + compaction:
    //   f[2] = batch; pass A: gate f[2] -> list[2], mark f[1]
    //   pass B: gate f[1] -> list[1], mark f[0]
    //   pass C: gate f[0] -> list[0]
    k_mark_batch<<<G_MARK, T>>>(user, pos, neg);
    k_compact<<<G_EDGES, T>>>(src, dst, 2, 1, 1);
    k_compact<<<G_EDGES, T>>>(src, dst, 1, 0, 1);
    k_compact<<<G_EDGES, T>>>(src, dst, 0, 0, 0);

    // zero exactly the rows each layer writes
    k_zero_list<<<G_ZERO, T>>>(1, 0);   // XA over nodelist L1
    k_zero_list<<<G_ZERO, T>>>(2, 1);   // XB over nodelist L2
    k_zero_list<<<G_ZERO, T>>>(3, 2);   // XC over nodelist L3

    // layer-0 term of the stacked mean
    k_init_acc<<<G_ACC, T>>>(emb, user, pos, neg);

    // layer 1: emb -> XA over list[0]
    k_prop_list<<<G_PROP, T>>>(emb, 0, 1, 0);
    k_gather_add<<<G_ACC, T>>>(1, user, pos, neg);

    // layer 2: XA -> XB over list[1]
    k_prop_list<<<G_PROP, T>>>(emb, 1, 2, 1);
    k_gather_add<<<G_ACC, T>>>(2, user, pos, neg);

    // layer 3: XB -> XC over list[2]
    k_prop_list<<<G_PROP, T>>>(emb, 2, 3, 2);
    k_gather_add<<<G_ACC, T>>>(3, user, pos, neg);

    // loss
    k_zero_out<<<1, 1>>>(out);
    k_loss<<<BATCH / 8, T>>>(emb, user, pos, neg, out);
}

// round 6
// speedup vs baseline: 6.5479x; 1.0287x over previous
#include <cuda_runtime.h>
#include <cstdint>
#include <cstddef>

#define N_USERS   100000
#define N_NODES   500000
#define DIM       64
#define N_EDGES   2000000
#define BATCH     4096

// -------- device scratch (static, allocation-free) --------
// NOTE: never touch these symbols from host code (GB300 ATS would silently
// route through the host shadow at 200GB/s). All access via device selectors.
__device__ float    g_XA[(size_t)N_NODES * DIM];
__device__ float    g_XB[(size_t)N_NODES * DIM];
__device__ float    g_XC[(size_t)N_NODES * DIM];
__device__ float    g_dinv[N_NODES];
__device__ unsigned g_deg[N_NODES];
__device__ int      g_f[3][N_NODES];       // needed-node flags (0=L1,1=L2,2=L3)
__device__ int      g_nl[3][N_NODES];      // compact node lists
__device__ int      g_ncnt[3];
__device__ int2     g_le[3][N_EDGES];      // compact edge lists (src,dst)
__device__ int      g_ecnt[3];

__device__ __forceinline__ float* xbuf(int sel) {
    return sel == 1 ? g_XA : (sel == 2 ? g_XB : g_XC);
}

// -------- init counters + flags --------
__global__ void k_init() {
    int i = blockIdx.x * blockDim.x + threadIdx.x;
    if (i < N_NODES) {
        g_deg[i] = 0u;
        g_f[0][i] = 0; g_f[1][i] = 0; g_f[2][i] = 0;
    }
    if (i < 3) { g_ncnt[i] = 0; g_ecnt[i] = 0; }
}

__global__ void k_deg(const int* __restrict__ dst) {
    int e = blockIdx.x * blockDim.x + threadIdx.x;
    if (e < N_EDGES) atomicAdd(&g_deg[dst[e]], 1u);
}

__global__ void k_dinv() {
    int i = blockIdx.x * blockDim.x + threadIdx.x;
    if (i < N_NODES) {
        unsigned d = g_deg[i];
        g_dinv[i] = d ? rsqrtf((float)d) : 0.0f;
    }
}

// mark batch nodes in all 3 flag sets + node lists; one (layer, slot) per thread
__global__ void k_mark_batch(const int* __restrict__ u,
                             const int* __restrict__ p,
                             const int* __restrict__ n) {
    int t = blockIdx.x * blockDim.x + threadIdx.x;
    if (t >= 9 * BATCH) return;
    int L = t / (3 * BATCH);
    int r = t - L * (3 * BATCH);
    int idx = (r < BATCH) ? u[r]
            : (r < 2 * BATCH) ? p[r - BATCH]
                              : n[r - 2 * BATCH];
    if (atomicExch(&g_f[L][idx], 1) == 0) {
        int s = atomicAdd(&g_ncnt[L], 1);
        g_nl[L][s] = idx;
    }
}

// compaction: gate on f[gate], append passing edges to list[gate];
// optionally mark sources as needed one layer earlier (+node list)
__global__ void k_compact(const int* __restrict__ src, const int* __restrict__ dst,
                          int gate, int prev, int has_prev) {
    int e = blockIdx.x * blockDim.x + threadIdx.x;
    if (e >= N_EDGES) return;
    int d = __ldg(dst + e);
    if (!g_f[gate][d]) return;
    int s = __ldg(src + e);
    int slot = atomicAdd(&g_ecnt[gate], 1);
    g_le[gate][slot] = make_int2(s, d);
    if (has_prev) {
        if (atomicExch(&g_f[prev][s], 1) == 0) {
            int ns = atomicAdd(&g_ncnt[prev], 1);
            g_nl[prev][ns] = s;
        }
    }
}

// zero exactly the rows in node list lsel of buffer xsel (grid-stride)
__global__ void k_zero_list(int xsel, int lsel) {
    int n16 = g_ncnt[lsel] * 16;
    float4* y = (float4*)xbuf(xsel);
    int stride = gridDim.x * blockDim.x;
    for (int t = blockIdx.x * blockDim.x + threadIdx.x; t < n16; t += stride) {
        int node = g_nl[lsel][t >> 4];
        y[(size_t)node * 16 + (t & 15)] = make_float4(0.f, 0.f, 0.f, 0.f);
    }
}

// propagation over compact edge list: 16 threads/edge, grid-stride.
// weight computed on the fly from L2-resident dinv (same addr across 16 lanes).
__global__ void k_prop_list(const float* __restrict__ emb, int xsel, int ysel, int lsel) {
    int m = g_ecnt[lsel] * 16;
    const float* x = (xsel == 0) ? emb : xbuf(xsel);
    float*       y = xbuf(ysel);
    int stride = gridDim.x * blockDim.x;
    for (int t = blockIdx.x * blockDim.x + threadIdx.x; t < m; t += stride) {
        int e = t >> 4, lane = t & 15;
        int2  sd = __ldg(&g_le[lsel][e]);
        float w = __ldg(g_dinv + sd.x) * __ldg(g_dinv + sd.y);
        float4 v = __ldg((const float4*)x + (size_t)sd.x * 16 + lane);
        float4* a = (float4*)y + (size_t)sd.y * 16 + lane;
        asm volatile("red.global.add.v4.f32 [%0], {%1, %2, %3, %4};"
                     :: "l"(a), "f"(v.x * w), "f"(v.y * w), "f"(v.z * w), "f"(v.w * w)
                     : "memory");
    }
}

__global__ void k_zero_out(float* out) {
    if (threadIdx.x == 0 && blockIdx.x == 0) out[0] = 0.0f;
}

// -------- fused final loss: one warp per batch element --------
// acc[idx] = emb[idx] + XA[idx] + XB[idx] + XC[idx]  (raw 4-layer sum; /4 folded
// into the 1/16 dot scale). batch ⊆ f3 ⊆ f2 ⊆ f1 so all buffers valid there.
__global__ void k_loss(const float* __restrict__ emb,
                       const int* __restrict__ user,
                       const int* __restrict__ pos,
                       const int* __restrict__ neg,
                       float* __restrict__ out) {
    int w = (blockIdx.x * blockDim.x + threadIdx.x) >> 5;
    int lane = threadIdx.x & 31;
    if (w >= BATCH) return;

    int ui = user[w], pi = pos[w], ni = neg[w];

    const float2* E = (const float2*)emb;
    const float2* A = (const float2*)g_XA;
    const float2* B = (const float2*)g_XB;
    const float2* C = (const float2*)g_XC;

    size_t uo = (size_t)ui * 32 + lane;
    size_t po = (size_t)pi * 32 + lane;
    size_t no = (size_t)ni * 32 + lane;

    float2 eu = __ldg(E + uo), ep = __ldg(E + po), en = __ldg(E + no);

    float2 au = __ldg(A + uo), bu = __ldg(B + uo), cu = __ldg(C + uo);
    float2 ap = __ldg(A + po), bp = __ldg(B + po), cp = __ldg(C + po);
    float2 an = __ldg(A + no), bn = __ldg(B + no), cn = __ldg(C + no);

    float ux = eu.x + au.x + bu.x + cu.x, uy = eu.y + au.y + bu.y + cu.y;
    float px = ep.x + ap.x + bp.x + cp.x, py = ep.y + ap.y + bp.y + cp.y;
    float nx = en.x + an.x + bn.x + cn.x, ny = en.y + an.y + bn.y + cn.y;

    float pd = ux * px + uy * py;
    float nd = ux * nx + uy * ny;
    float sq = eu.x * eu.x + eu.y * eu.y
             + ep.x * ep.x + ep.y * ep.y
             + en.x * en.x + en.y * en.y;

#pragma unroll
    for (int o = 16; o; o >>= 1) {
        pd += __shfl_xor_sync(0xffffffffu, pd, o);
        nd += __shfl_xor_sync(0xffffffffu, nd, o);
        sq += __shfl_xor_sync(0xffffffffu, sq, o);
    }
    if (lane == 0) {
        float z = (nd - pd) * 0.0625f;                       // /16 for mean^2
        float sp = fmaxf(z, 0.f) + log1pf(expf(-fabsf(z)));  // softplus(neg-pos)
        atomicAdd(out, (sp + 5e-5f * sq) * (1.0f / BATCH));  // + L2_REG*0.5/BATCH
    }
}

extern "C" void kernel_launch(void* const* d_in, const int* in_sizes, int n_in,
                              void* d_out, int out_size) {
    const float* emb  = (const float*)d_in[0];
    const int*   edge = (const int*)d_in[1];
    const int*   src  = edge;
    const int*   dst  = edge + N_EDGES;
    const int*   user = (const int*)d_in[2];
    const int*   pos  = (const int*)d_in[3];
    const int*   neg  = (const int*)d_in[4];
    float*       out  = (float*)d_out;

    // streams + events created once, reused (no device-memory allocation)
    static cudaStream_t s1 = nullptr, s2 = nullptr;
    static cudaEvent_t evInit, evMark, evA, evB, evC, evZ;
    if (!s1) {
        cudaStreamCreateWithFlags(&s1, cudaStreamNonBlocking);
        cudaStreamCreateWithFlags(&s2, cudaStreamNonBlocking);
        cudaEventCreateWithFlags(&evInit, cudaEventDisableTiming);
        cudaEventCreateWithFlags(&evMark, cudaEventDisableTiming);
        cudaEventCreateWithFlags(&evA,    cudaEventDisableTiming);
        cudaEventCreateWithFlags(&evB,    cudaEventDisableTiming);
        cudaEventCreateWithFlags(&evC,    cudaEventDisableTiming);
        cudaEventCreateWithFlags(&evZ,    cudaEventDisableTiming);
    }

    const int T = 256;
    const int G_NODES = (N_NODES + T - 1) / T;
    const int G_EDGES = (N_EDGES + T - 1) / T;
    const int G_MARK  = (9 * BATCH + T - 1) / T;
    const int G_PROP  = 2048;
    const int G_ZERO  = 1024;

    // origin stream: init, then fork
    k_init<<<G_NODES, T>>>();
    cudaEventRecord(evInit, 0);

    // chain 1 (origin stream): degree -> dinv  (needed only by the props)
    k_deg<<<G_EDGES, T>>>(dst);
    k_dinv<<<G_NODES, T>>>();

    // chain 2 (s1): mark -> compact x3
    cudaStreamWaitEvent(s1, evInit, 0);
    k_mark_batch<<<G_MARK, T, 0, s1>>>(user, pos, neg);
    cudaEventRecord(evMark, s1);
    k_compact<<<G_EDGES, T, 0, s1>>>(src, dst, 2, 1, 1);   // L3 edges; mark f2
    cudaEventRecord(evA, s1);
    k_compact<<<G_EDGES, T, 0, s1>>>(src, dst, 1, 0, 1);   // L2 edges; mark f1
    cudaEventRecord(evB, s1);
    k_compact<<<G_EDGES, T, 0, s1>>>(src, dst, 0, 0, 0);   // L1 edges
    cudaEventRecord(evC, s1);

    // chain 3 (s2): zero each output buffer as soon as its node list is final
    cudaStreamWaitEvent(s2, evMark, 0);
    k_zero_list<<<G_ZERO, T, 0, s2>>>(3, 2);               // XC over f3 list
    cudaStreamWaitEvent(s2, evA, 0);
    k_zero_list<<<G_ZERO, T, 0, s2>>>(2, 1);               // XB over f2 list
    cudaStreamWaitEvent(s2, evB, 0);
    k_zero_list<<<G_ZERO, T, 0, s2>>>(1, 0);               // XA over f1 list
    cudaEventRecord(evZ, s2);

    // join everything back onto the origin stream
    cudaStreamWaitEvent(0, evC, 0);
    cudaStreamWaitEvent(0, evZ, 0);

    // props (weights from dinv on the fly)
    k_prop_list<<<G_PROP, T>>>(emb, 0, 1, 0);              // emb -> XA over list0
    k_prop_list<<<G_PROP, T>>>(emb, 1, 2, 1);              // XA  -> XB over list1
    k_prop_list<<<G_PROP, T>>>(emb, 2, 3, 2);              // XB  -> XC over list2

    // fused loss
    k_zero_out<<<1, 1>>>(out);
    k_loss<<<BATCH / 8, T>>>(emb, user, pos, neg, out);
}

// round 8
// speedup vs baseline: 7.3411x; 1.1211x over previous
#include <cuda_runtime.h>
#include <cstdint>
#include <cstddef>

#define N_USERS   100000
#define N_NODES   500000
#define DIM       64
#define N_EDGES   2000000
#define BATCH     4096

// -------- device scratch (static, allocation-free) --------
// NOTE: never touch these symbols from host code (GB300 ATS would silently
// route through the host shadow at 200GB/s). All access via device selectors.
__device__ float    g_XA[(size_t)N_NODES * DIM];
__device__ float    g_XB[(size_t)N_NODES * DIM];
__device__ float    g_XC[(size_t)N_NODES * DIM];
__device__ float    g_dinv[N_NODES];
__device__ unsigned g_deg[N_NODES];
__device__ int      g_f[3][N_NODES];       // needed-node flags (0=L1,1=L2,2=L3)
__device__ int      g_nl[3][N_NODES];      // compact node lists
__device__ int      g_ncnt[3];
__device__ int2     g_le[3][N_EDGES];      // compact edge lists (src,dst)
__device__ int      g_ecnt[3];

__device__ __forceinline__ float* xbuf(int sel) {
    return sel == 1 ? g_XA : (sel == 2 ? g_XB : g_XC);
}

// -------- init counters + flags --------
__global__ void k_init() {
    int i = blockIdx.x * blockDim.x + threadIdx.x;
    if (i < N_NODES) {
        g_deg[i] = 0u;
        g_f[0][i] = 0; g_f[1][i] = 0; g_f[2][i] = 0;
    }
    if (i < 3) { g_ncnt[i] = 0; g_ecnt[i] = 0; }
}

__global__ void k_deg(const int* __restrict__ dst) {
    int e = blockIdx.x * blockDim.x + threadIdx.x;
    if (e < N_EDGES) atomicAdd(&g_deg[dst[e]], 1u);
}

__global__ void k_dinv() {
    int i = blockIdx.x * blockDim.x + threadIdx.x;
    if (i < N_NODES) {
        unsigned d = g_deg[i];
        g_dinv[i] = d ? rsqrtf((float)d) : 0.0f;
    }
}

// warp-aggregated list append: returns this lane's slot (valid where pred)
__device__ __forceinline__ int wagg_append(int* counter, bool pred) {
    unsigned mask = __ballot_sync(0xffffffffu, pred);
    if (!pred) return -1;
    int lane   = threadIdx.x & 31;
    int leader = __ffs(mask) - 1;
    int rank   = __popc(mask & ((1u << lane) - 1));
    int base = 0;
    if (lane == leader) base = atomicAdd(counter, __popc(mask));
    base = __shfl_sync(mask, base, leader);
    return base + rank;
}

// mark batch nodes in all 3 flag sets + node lists; one (layer, slot) per thread
__global__ void k_mark_batch(const int* __restrict__ u,
                             const int* __restrict__ p,
                             const int* __restrict__ n) {
    int t = blockIdx.x * blockDim.x + threadIdx.x;
    bool act = (t < 9 * BATCH);
    int L = 0, idx = 0;
    if (act) {
        L = t / (3 * BATCH);
        int r = t - L * (3 * BATCH);
        idx = (r < BATCH) ? u[r]
            : (r < 2 * BATCH) ? p[r - BATCH]
                              : n[r - 2 * BATCH];
        act = (atomicExch(&g_f[L][idx], 1) == 0);
    }
#pragma unroll
    for (int LL = 0; LL < 3; LL++) {
        bool pred = act && (L == LL);
        int slot = wagg_append(&g_ncnt[LL], pred);
        if (pred) g_nl[LL][slot] = idx;
    }
}

// compaction: gate on f[gate], append passing edges to list[gate];
// optionally mark sources as needed one layer earlier (+node list)
__global__ void k_compact(const int* __restrict__ src, const int* __restrict__ dst,
                          int gate, int prev, int has_prev) {
    int e = blockIdx.x * blockDim.x + threadIdx.x;
    bool pass = false;
    int s = 0, d = 0;
    if (e < N_EDGES) {
        d = __ldg(dst + e);
        pass = (g_f[gate][d] != 0);
        if (pass) s = __ldg(src + e);
    }
    int slot = wagg_append(&g_ecnt[gate], pass);
    if (pass) g_le[gate][slot] = make_int2(s, d);

    if (has_prev) {
        bool nw = pass && (atomicExch(&g_f[prev][s], 1) == 0);
        int ns = wagg_append(&g_ncnt[prev], nw);
        if (nw) g_nl[prev][ns] = s;
    }
}

// zero exactly the rows in node list lsel of buffer xsel (grid-stride)
__global__ void k_zero_list(int xsel, int lsel) {
    int n16 = g_ncnt[lsel] * 16;
    float4* y = (float4*)xbuf(xsel);
    int stride = gridDim.x * blockDim.x;
    for (int t = blockIdx.x * blockDim.x + threadIdx.x; t < n16; t += stride) {
        int node = g_nl[lsel][t >> 4];
        y[(size_t)node * 16 + (t & 15)] = make_float4(0.f, 0.f, 0.f, 0.f);
    }
}

// propagation over compact edge list: 16 threads/edge, grid-stride.
// weight computed on the fly from L2-resident dinv (broadcast across lanes).
__global__ void k_prop_list(const float* __restrict__ emb, int xsel, int ysel, int lsel) {
    int m = g_ecnt[lsel] * 16;
    const float* x = (xsel == 0) ? emb : xbuf(xsel);
    float*       y = xbuf(ysel);
    int stride = gridDim.x * blockDim.x;
    for (int t = blockIdx.x * blockDim.x + threadIdx.x; t < m; t += stride) {
        int e = t >> 4, lane = t & 15;
        int2  sd = __ldg(&g_le[lsel][e]);
        float w = __ldg(g_dinv + sd.x) * __ldg(g_dinv + sd.y);
        float4 v = __ldg((const float4*)x + (size_t)sd.x * 16 + lane);
        float4* a = (float4*)y + (size_t)sd.y * 16 + lane;
        asm volatile("red.global.add.v4.f32 [%0], {%1, %2, %3, %4};"
                     :: "l"(a), "f"(v.x * w), "f"(v.y * w), "f"(v.z * w), "f"(v.w * w)
                     : "memory");
    }
}

__global__ void k_zero_out(float* out) {
    if (threadIdx.x == 0 && blockIdx.x == 0) out[0] = 0.0f;
}

// -------- fused final loss: one warp per batch element --------
__global__ void k_loss(const float* __restrict__ emb,
                       const int* __restrict__ user,
                       const int* __restrict__ pos,
                       const int* __restrict__ neg,
                       float* __restrict__ out) {
    int w = (blockIdx.x * blockDim.x + threadIdx.x) >> 5;
    int lane = threadIdx.x & 31;
    if (w >= BATCH) return;

    int ui = user[w], pi = pos[w], ni = neg[w];

    const float2* E = (const float2*)emb;
    const float2* A = (const float2*)g_XA;
    const float2* B = (const float2*)g_XB;
    const float2* C = (const float2*)g_XC;

    size_t uo = (size_t)ui * 32 + lane;
    size_t po = (size_t)pi * 32 + lane;
    size_t no = (size_t)ni * 32 + lane;

    float2 eu = __ldg(E + uo), ep = __ldg(E + po), en = __ldg(E + no);
    float2 au = __ldg(A + uo), bu = __ldg(B + uo), cu = __ldg(C + uo);
    float2 ap = __ldg(A + po), bp = __ldg(B + po), cp = __ldg(C + po);
    float2 an = __ldg(A + no), bn = __ldg(B + no), cn = __ldg(C + no);

    float ux = eu.x + au.x + bu.x + cu.x, uy = eu.y + au.y + bu.y + cu.y;
    float px = ep.x + ap.x + bp.x + cp.x, py = ep.y + ap.y + bp.y + cp.y;
    float nx = en.x + an.x + bn.x + cn.x, ny = en.y + an.y + bn.y + cn.y;

    float pd = ux * px + uy * py;
    float nd = ux * nx + uy * ny;
    float sq = eu.x * eu.x + eu.y * eu.y
             + ep.x * ep.x + ep.y * ep.y
             + en.x * en.x + en.y * en.y;

#pragma unroll
    for (int o = 16; o; o >>= 1) {
        pd += __shfl_xor_sync(0xffffffffu, pd, o);
        nd += __shfl_xor_sync(0xffffffffu, nd, o);
        sq += __shfl_xor_sync(0xffffffffu, sq, o);
    }
    if (lane == 0) {
        float z = (nd - pd) * 0.0625f;                       // /16 for mean^2
        float sp = fmaxf(z, 0.f) + log1pf(expf(-fabsf(z)));  // softplus(neg-pos)
        atomicAdd(out, (sp + 5e-5f * sq) * (1.0f / BATCH));  // + L2_REG*0.5/BATCH
    }
}

extern "C" void kernel_launch(void* const* d_in, const int* in_sizes, int n_in,
                              void* d_out, int out_size) {
    const float* emb  = (const float*)d_in[0];
    const int*   edge = (const int*)d_in[1];
    const int*   src  = edge;
    const int*   dst  = edge + N_EDGES;
    const int*   user = (const int*)d_in[2];
    const int*   pos  = (const int*)d_in[3];
    const int*   neg  = (const int*)d_in[4];
    float*       out  = (float*)d_out;

    static cudaStream_t s1 = nullptr, s2 = nullptr;
    static cudaEvent_t evInit, evMark, evA, evB, evDinv, evZ;
    if (!s1) {
        cudaStreamCreateWithFlags(&s1, cudaStreamNonBlocking);
        cudaStreamCreateWithFlags(&s2, cudaStreamNonBlocking);
        cudaEventCreateWithFlags(&evInit, cudaEventDisableTiming);
        cudaEventCreateWithFlags(&evMark, cudaEventDisableTiming);
        cudaEventCreateWithFlags(&evA,    cudaEventDisableTiming);
        cudaEventCreateWithFlags(&evB,    cudaEventDisableTiming);
        cudaEventCreateWithFlags(&evDinv, cudaEventDisableTiming);
        cudaEventCreateWithFlags(&evZ,    cudaEventDisableTiming);
    }

    const int T = 256;
    const int G_NODES = (N_NODES + T - 1) / T;
    const int G_EDGES = (N_EDGES + T - 1) / T;
    const int G_MARK  = (9 * BATCH + T - 1) / T;
    const int G_PROP  = 2048;
    const int G_ZERO  = 1024;

    // origin stream: the serial critical chain (init -> mark -> compact x3)
    k_init<<<G_NODES, T>>>();
    cudaEventRecord(evInit, 0);
    k_mark_batch<<<G_MARK, T>>>(user, pos, neg);
    cudaEventRecord(evMark, 0);
    k_compact<<<G_EDGES, T>>>(src, dst, 2, 1, 1);   // L3 edges; mark f2 (+nl1)
    cudaEventRecord(evA, 0);
    k_compact<<<G_EDGES, T>>>(src, dst, 1, 0, 1);   // L2 edges; mark f1 (+nl0)
    cudaEventRecord(evB, 0);
    k_compact<<<G_EDGES, T>>>(src, dst, 0, 0, 0);   // L1 edges

    // side chain (s1): deg -> dinv, needed only by the props; starts after init.
    // First s1 op is the event wait -> s1 joins the graph capture correctly.
    cudaStreamWaitEvent(s1, evInit, 0);
    k_deg<<<G_EDGES, T, 0, s1>>>(dst);
    k_dinv<<<G_NODES, T, 0, s1>>>();
    cudaEventRecord(evDinv, s1);

    // side chain (s2): MUST join capture via event-wait BEFORE any launch
    // (a launch on a side stream before its first wait is NOT captured -> the
    // zero would vanish from timed replays; that was the R7 failure).
    cudaStreamWaitEvent(s2, evMark, 0);
    k_zero_out<<<1, 1, 0, s2>>>(out);
    k_zero_list<<<G_ZERO, T, 0, s2>>>(3, 2);        // XC over nl2 (final at mark)
    cudaStreamWaitEvent(s2, evA, 0);
    k_zero_list<<<G_ZERO, T, 0, s2>>>(2, 1);        // XB over nl1 (final at compactA)
    cudaStreamWaitEvent(s2, evB, 0);
    k_zero_list<<<G_ZERO, T, 0, s2>>>(1, 0);        // XA over nl0 (final at compactB)
    cudaEventRecord(evZ, s2);

    // join side chains onto origin before the props
    cudaStreamWaitEvent(0, evDinv, 0);
    cudaStreamWaitEvent(0, evZ, 0);

    // props (weights from dinv on the fly)
    k_prop_list<<<G_PROP, T>>>(emb, 0, 1, 0);       // emb -> XA over list0
    k_prop_list<<<G_PROP, T>>>(emb, 1, 2, 1);       // XA  -> XB over list1
    k_prop_list<<<G_PROP, T>>>(emb, 2, 3, 2);       // XB  -> XC over list2

    // fused loss (out zeroed on s2, ordered via evZ)
    k_loss<<<BATCH / 8, T>>>(emb, user, pos, neg, out);
}